// round 13
// baseline (speedup 1.0000x reference)
#include <cuda_runtime.h>
#include <cuda_bf16.h>
#include <cstdint>

// Problem constants
#define BATCH 2
#define SEQ   2048
#define EMB   1024
#define HEADS 16
#define HDIM  64
#define ROWS  (BATCH * SEQ)   // 4096
#define GK 1024
#define GN 1024
#define RP    (EMB / 2)       // packed uint32 per row = 512
#define N2X   (ROWS * RP)     // 2M
#define N2W   (EMB * RP)      // 512K

// ---------------------------------------------------------------------------
// Scratch: packed bf16x2 hi/lo representations (QKV contiguous)
// ---------------------------------------------------------------------------
__device__ uint32_t g_xh[N2X], g_xl[N2X];
__device__ uint32_t g_wh[4 * N2W], g_wl[4 * N2W];       // Wq,Wk,Wv,Wo
__device__ uint32_t g_QKVh[3 * N2X], g_QKVl[3 * N2X];   // Q,K,V contiguous
__device__ uint32_t g_Ch[N2X], g_Cl[N2X];

// ---------------------------------------------------------------------------
// Helpers
// ---------------------------------------------------------------------------
__device__ __forceinline__ uint32_t smem_to_u32(const void* p) {
    uint32_t a;
    asm("{ .reg .u64 t; cvta.to.shared.u64 t, %1; cvt.u32.u64 %0, t; }"
        : "=r"(a) : "l"(p));
    return a;
}

__device__ __forceinline__ void ldsm_x4(uint32_t r[4], uint32_t addr) {
    asm volatile("ldmatrix.sync.aligned.m8n8.x4.shared.b16 {%0,%1,%2,%3}, [%4];"
                 : "=r"(r[0]), "=r"(r[1]), "=r"(r[2]), "=r"(r[3]) : "r"(addr));
}

__device__ __forceinline__ void ldsm_x4_t(uint32_t r[4], uint32_t addr) {
    asm volatile("ldmatrix.sync.aligned.m8n8.x4.trans.shared.b16 {%0,%1,%2,%3}, [%4];"
                 : "=r"(r[0]), "=r"(r[1]), "=r"(r[2]), "=r"(r[3]) : "r"(addr));
}

__device__ __forceinline__ void mma_bf16(float c[4],
    uint32_t a0, uint32_t a1, uint32_t a2, uint32_t a3,
    uint32_t b0, uint32_t b1)
{
    asm volatile(
        "mma.sync.aligned.m16n8k16.row.col.f32.bf16.bf16.f32 "
        "{%0,%1,%2,%3}, {%4,%5,%6,%7}, {%8,%9}, {%0,%1,%2,%3};"
        : "+f"(c[0]), "+f"(c[1]), "+f"(c[2]), "+f"(c[3])
        : "r"(a0), "r"(a1), "r"(a2), "r"(a3), "r"(b0), "r"(b1));
}

// split fp32 pair -> packed bf16x2 hi (lo16=x, hi16=y) and lo (residuals)
__device__ __forceinline__ void split2(float x, float y, uint32_t& hi, uint32_t& lo)
{
    uint32_t h;
    asm("cvt.rn.bf16x2.f32 %0, %1, %2;" : "=r"(h) : "f"(y), "f"(x));
    float hx = __uint_as_float(h << 16);
    float hy = __uint_as_float(h & 0xffff0000u);
    float lx = x - hx, ly = y - hy;
    uint32_t l;
    asm("cvt.rn.bf16x2.f32 %0, %1, %2;" : "=r"(l) : "f"(ly), "f"(lx));
    hi = h; lo = l;
}

// cp.async
#define CP16(smem, gptr) \
    asm volatile("cp.async.cg.shared.global [%0], [%1], 16;" \
                 :: "r"(smem), "l"(gptr) : "memory")
#define CP4(smem, gptr) \
    asm volatile("cp.async.ca.shared.global [%0], [%1], 4;" \
                 :: "r"(smem), "l"(gptr) : "memory")
#define CP_COMMIT() asm volatile("cp.async.commit_group;" ::: "memory")
#define CP_WAIT0()  asm volatile("cp.async.wait_group 0;" ::: "memory")
#define CP_WAIT1()  asm volatile("cp.async.wait_group 1;" ::: "memory")
#define CP_WAIT2()  asm volatile("cp.async.wait_group 2;" ::: "memory")

// ---------------------------------------------------------------------------
// Fused pre-conversion: x + all 4 weights in ONE launch, 4-wide vectorized
// ---------------------------------------------------------------------------
__global__ void cvt_all(const float* __restrict__ x,
                        const float* __restrict__ Wq, const float* __restrict__ Wk,
                        const float* __restrict__ Wv, const float* __restrict__ Wo,
                        uint32_t* __restrict__ xh, uint32_t* __restrict__ xl,
                        uint32_t* __restrict__ wh, uint32_t* __restrict__ wl)
{
    int q = blockIdx.x * blockDim.x + threadIdx.x;   // quad index (4 uint32 each)
    const int NQX = N2X / 4, NQW = N2W / 4;
    if (q >= NQX + 4 * NQW) return;
    const float* src;
    uint32_t *dh, *dl;
    int j;
    if (q < NQX) {
        src = x; dh = xh; dl = xl; j = q;
    } else {
        int t = (q - NQX) / NQW;
        j = (q - NQX) - t * NQW;
        src = (t == 0) ? Wq : (t == 1) ? Wk : (t == 2) ? Wv : Wo;
        dh = wh + (size_t)t * N2W;
        dl = wl + (size_t)t * N2W;
    }
    float4 v0 = ((const float4*)src)[j * 2];
    float4 v1 = ((const float4*)src)[j * 2 + 1];
    uint4 hi, lo;
    split2(v0.x, v0.y, hi.x, lo.x);
    split2(v0.z, v0.w, hi.y, lo.y);
    split2(v1.x, v1.y, hi.z, lo.z);
    split2(v1.z, v1.w, hi.w, lo.w);
    ((uint4*)dh)[j] = hi;
    ((uint4*)dl)[j] = lo;
}

// ===========================================================================
// HMMA NT GEMM on pre-split bf16 inputs (R10/R12 champion, byte-identical).
// 3-stage cp.async ring, ONE __syncthreads per K-chunk, 2 CTAs/SM.
// ===========================================================================
#define OFF_AHI 0
#define OFF_ALO 8192
#define OFF_BHI 16384
#define OFF_BLO 24576
#define STAGE_B 32768
#define GEMM_SMEM (3 * STAGE_B)          // 98304 B

#define GSWZ(row, g) ((uint32_t)((row) * 64 + (((g) ^ (((row) >> 1) & 3)) << 4)))

__global__ __launch_bounds__(256, 2) void gemm_bf(
    const uint32_t* __restrict__ Ah, const uint32_t* __restrict__ Al,
    const uint32_t* __restrict__ Bh_base, const uint32_t* __restrict__ Bl_base,
    float* __restrict__ Cf,
    uint32_t* __restrict__ Ch_base, uint32_t* __restrict__ Cl_base)
{
    extern __shared__ char smc[];
    const uint32_t sbase = smem_to_u32(smc);
    const int tid  = threadIdx.x;
    const int lane = tid & 31;
    const int w    = tid >> 5;
    const int wm   = w >> 2;
    const int wn   = w & 3;
    const int mat  = blockIdx.x >> 3;            // 0 for single-mat grids
    const int bn   = (blockIdx.x & 7) * 128;
    const int bm   = blockIdx.y * 128;

    const uint32_t* Bh = Bh_base + (size_t)mat * N2W;
    const uint32_t* Bl = Bl_base + (size_t)mat * N2W;
    uint32_t* Ch = Ch_base ? Ch_base + (size_t)mat * N2X : nullptr;
    uint32_t* Cl = Cl_base ? Cl_base + (size_t)mat * N2X : nullptr;

    float acc[4][4][4];
    #pragma unroll
    for (int i = 0; i < 4; i++)
        #pragma unroll
        for (int j = 0; j < 4; j++)
            #pragma unroll
            for (int q = 0; q < 4; q++) acc[i][j][q] = 0.f;

    // issue one K-chunk c into stage c%3
    auto issue = [&](int c) {
        const uint32_t stg = (uint32_t)(c % 3) * STAGE_B;
        #pragma unroll
        for (int u = 0; u < 8; ++u) {
            const int half = u >> 1;                 // 0:Ah 1:Al 2:Bh 3:Bl
            const int rem  = ((u & 1) << 8) + tid;   // 0..511
            const int row  = rem >> 2;
            const int seg  = rem & 3;
            const int grow = (half < 2 ? bm : bn) + row;
            const uint32_t* gp =
                (half == 0 ? Ah : half == 1 ? Al : half == 2 ? Bh : Bl)
                + (size_t)grow * RP + c * 16 + seg * 4;
            uint32_t sa = sbase + stg + (uint32_t)(half * 8192) + GSWZ(row, seg);
            CP16(sa, gp);
        }
        CP_COMMIT();
    };

    const int NCH = GK / 32;   // 32
    issue(0);
    issue(1);

    for (int it = 0; it < NCH; ++it) {
        if (it < NCH - 1) { CP_WAIT1(); } else { CP_WAIT0(); }
        __syncthreads();
        if (it + 2 < NCH) issue(it + 2);   // stage (it+2)%3 == (it-1)%3, consumed

        const uint32_t sb = sbase + (uint32_t)(it % 3) * STAGE_B;
        #pragma unroll
        for (int ks = 0; ks < 2; ++ks) {
            uint32_t ah[4][4], al[4][4], bh[2][4], bl[2][4];
            const int g = ks * 2 + (lane >> 4);      // granule 0..3
            const int arow = wm * 64 + (lane & 15);
            #pragma unroll
            for (int ms = 0; ms < 4; ++ms) {
                uint32_t off = GSWZ(arow + ms * 16, g);
                ldsm_x4(ah[ms], sb + OFF_AHI + off);
                ldsm_x4(al[ms], sb + OFF_ALO + off);
            }
            const int brow = wn * 32 + (lane & 15);
            #pragma unroll
            for (int pr = 0; pr < 2; ++pr) {
                uint32_t off = GSWZ(brow + pr * 16, g);
                ldsm_x4(bh[pr], sb + OFF_BHI + off);
                ldsm_x4(bl[pr], sb + OFF_BLO + off);
            }
            #pragma unroll
            for (int ms = 0; ms < 4; ++ms)
                #pragma unroll
                for (int ns = 0; ns < 4; ++ns) {
                    const int pr = ns >> 1, od = ns & 1;
                    mma_bf16(acc[ms][ns], ah[ms][0], ah[ms][1], ah[ms][2], ah[ms][3],
                             bh[pr][od], bh[pr][od + 2]);
                    mma_bf16(acc[ms][ns], ah[ms][0], ah[ms][1], ah[ms][2], ah[ms][3],
                             bl[pr][od], bl[pr][od + 2]);
                    mma_bf16(acc[ms][ns], al[ms][0], al[ms][1], al[ms][2], al[ms][3],
                             bh[pr][od], bh[pr][od + 2]);
                }
        }
    }

    // ---- epilogue
    #pragma unroll
    for (int ms = 0; ms < 4; ++ms) {
        const int row0 = bm + wm * 64 + ms * 16 + (lane >> 2);
        #pragma unroll
        for (int ns = 0; ns < 4; ++ns) {
            const int col = bn + wn * 32 + ns * 8 + (lane & 3) * 2;
            if (Cf) {
                *(float2*)&Cf[(size_t)row0 * GN + col] =
                    make_float2(acc[ms][ns][0], acc[ms][ns][1]);
                *(float2*)&Cf[(size_t)(row0 + 8) * GN + col] =
                    make_float2(acc[ms][ns][2], acc[ms][ns][3]);
            } else {
                uint32_t h, l;
                split2(acc[ms][ns][0], acc[ms][ns][1], h, l);
                Ch[(size_t)row0 * RP + (col >> 1)] = h;
                Cl[(size_t)row0 * RP + (col >> 1)] = l;
                split2(acc[ms][ns][2], acc[ms][ns][3], h, l);
                Ch[(size_t)(row0 + 8) * RP + (col >> 1)] = h;
                Cl[(size_t)(row0 + 8) * RP + (col >> 1)] = l;
            }
        }
    }
}

// ===========================================================================
// Tensor-core flash attention, 256 q-rows per CTA, 16 warps (512 threads).
// Per-warp math identical to the R12 champion; only the load maps changed.
// 2-stage cp.async KV ring at distance 2; resident Q smem; Q-lo reloaded
// per tile. Halves redundant KV traffic (8 CTAs per (b,h) instead of 16).
// ===========================================================================
#define FS_LD    144
#define F_KLO    9216
#define F_VHI    18432
#define F_VLO    27648
#define KV_STG   36864                  // bytes per stage
#define FBIAS    (2 * KV_STG)           // 73728: 2 x 64 ints
#define FQ_HI    (FBIAS + 2 * 256)      // 74240
#define FQ_LO    (FQ_HI + 36864)        // 111104  (256 rows x 144 B)
#define FA_SMEM  (FQ_LO + 36864)        // 147968 B (1 CTA/SM)

__global__ __launch_bounds__(512, 1) void flash_tc(
    const uint32_t* __restrict__ Qh_g, const uint32_t* __restrict__ Ql_g,
    const uint32_t* __restrict__ Kh_g, const uint32_t* __restrict__ Kl_g,
    const uint32_t* __restrict__ Vh_g, const uint32_t* __restrict__ Vl_g,
    const int* __restrict__ mask,
    uint32_t* __restrict__ Ch, uint32_t* __restrict__ Cl)
{
    extern __shared__ char smc[];
    const uint32_t sbase = smem_to_u32(smc);
    const int tid  = threadIdx.x;
    const int lane = tid & 31;
    const int w    = tid >> 5;          // 0..15
    const int q0 = blockIdx.x * 256;
    const int h  = blockIdx.y;
    const int b  = blockIdx.z;

    const size_t rbase = (size_t)b * SEQ;
    const int hoff = h * (HDIM / 2);    // packed col offset = h*32
    const int* mb = mask + rbase;

    auto issueKV = [&](int t) {
        const uint32_t stg = (uint32_t)(t & 1) * KV_STG;
        const int kv0 = t * 64;
        const int row = tid >> 3;       // 0..63
        const int seg = tid & 7;
        #pragma unroll
        for (int half = 0; half < 4; ++half) {   // 0:Kh 1:Kl 2:Vh 3:Vl
            const uint32_t* gp =
                (half == 0 ? Kh_g : half == 1 ? Kl_g : half == 2 ? Vh_g : Vl_g)
                + (rbase + kv0 + row) * RP + hoff + seg * 4;
            uint32_t sa = sbase + stg + (uint32_t)(half * 9216 + row * FS_LD + seg * 16);
            CP16(sa, gp);
        }
        if (tid < 64)
            CP4(sbase + FBIAS + (uint32_t)((t & 1) * 256 + tid * 4), mb + kv0 + tid);
        CP_COMMIT();
    };

    // ---- issue Q (256 rows x 2 halves), then KV tiles 0,1
    {
        #pragma unroll
        for (int u = 0; u < 8; ++u) {
            const int half = u >> 2;
            const int rem  = ((u & 3) << 9) + tid;   // 0..2047
            const int row  = rem >> 3;               // 0..255
            const int seg  = rem & 7;
            const uint32_t* gp = (half ? Ql_g : Qh_g) +
                (rbase + q0 + row) * RP + hoff + seg * 4;
            uint32_t sa = sbase + (half ? FQ_LO : FQ_HI) +
                          (uint32_t)(row * FS_LD + seg * 16);
            CP16(sa, gp);
        }
        CP_COMMIT();
    }
    issueKV(0);
    issueKV(1);

    CP_WAIT2();          // Q group complete
    __syncthreads();

    // ---- Q-hi fragments register-resident; Q-lo reloaded per tile
    uint32_t qh[4][4];
    #pragma unroll
    for (int ks = 0; ks < 4; ++ks) {
        uint32_t off = (uint32_t)((w * 16 + (lane & 15)) * FS_LD +
                                  (ks * 16 + ((lane >> 4) << 3)) * 2);
        ldsm_x4(qh[ks], sbase + FQ_HI + off);
    }

    float oacc[8][4];
    #pragma unroll
    for (int j = 0; j < 8; ++j)
        #pragma unroll
        for (int q = 0; q < 4; ++q) oacc[j][q] = 0.f;
    float mrow0 = -1e30f, mrow1 = -1e30f, lrow0 = 0.f, lrow1 = 0.f;

    const int NT = SEQ / 64;   // 32

    for (int it = 0; it < NT; ++it) {
        if (it < NT - 1) { CP_WAIT1(); } else { CP_WAIT0(); }
        __syncthreads();

        const int sti = it & 1;
        const uint32_t sb = sbase + (uint32_t)sti * KV_STG;

        // ---- S = Q K^T : split-bf16 3-pass; ks outer so ql is transient
        float s[8][4];
        #pragma unroll
        for (int j = 0; j < 8; ++j)
            #pragma unroll
            for (int q = 0; q < 4; ++q) s[j][q] = 0.f;

        #pragma unroll
        for (int ks = 0; ks < 4; ++ks) {
            uint32_t ql[4];
            uint32_t qoff = (uint32_t)((w * 16 + (lane & 15)) * FS_LD +
                                       (ks * 16 + ((lane >> 4) << 3)) * 2);
            ldsm_x4(ql, sbase + FQ_LO + qoff);
            #pragma unroll
            for (int pr = 0; pr < 4; ++pr) {
                uint32_t kh[4], kl[4];
                uint32_t off = (uint32_t)(((lane & 15) + pr * 16) * FS_LD +
                                          (ks * 16 + ((lane >> 4) << 3)) * 2);
                ldsm_x4(kh, sb + off);
                ldsm_x4(kl, sb + F_KLO + off);
                #pragma unroll
                for (int od = 0; od < 2; ++od) {
                    const int j = pr * 2 + od;
                    mma_bf16(s[j], qh[ks][0], qh[ks][1], qh[ks][2], qh[ks][3],
                             kh[od], kh[od + 2]);
                    mma_bf16(s[j], qh[ks][0], qh[ks][1], qh[ks][2], qh[ks][3],
                             kl[od], kl[od + 2]);
                    mma_bf16(s[j], ql[0], ql[1], ql[2], ql[3],
                             kh[od], kh[od + 2]);
                }
            }
        }

        // ---- scale + mask bias
        const float scale = 0.125f;   // 1/sqrt(64)
        #pragma unroll
        for (int j = 0; j < 8; ++j) {
            int2 mm = *(int2*)(smc + FBIAS + sti * 256 +
                               (j * 8 + (lane & 3) * 2) * 4);
            const float bx = mm.x ? 0.f : -1e30f;
            const float by = mm.y ? 0.f : -1e30f;
            s[j][0] = s[j][0] * scale + bx;
            s[j][1] = s[j][1] * scale + by;
            s[j][2] = s[j][2] * scale + bx;
            s[j][3] = s[j][3] * scale + by;
        }

        // ---- online softmax (rows on quads: shfl_xor 1,2)
        float rm0 = -1e30f, rm1 = -1e30f;
        #pragma unroll
        for (int j = 0; j < 8; ++j) {
            rm0 = fmaxf(rm0, fmaxf(s[j][0], s[j][1]));
            rm1 = fmaxf(rm1, fmaxf(s[j][2], s[j][3]));
        }
        rm0 = fmaxf(rm0, __shfl_xor_sync(0xffffffffu, rm0, 1));
        rm0 = fmaxf(rm0, __shfl_xor_sync(0xffffffffu, rm0, 2));
        rm1 = fmaxf(rm1, __shfl_xor_sync(0xffffffffu, rm1, 1));
        rm1 = fmaxf(rm1, __shfl_xor_sync(0xffffffffu, rm1, 2));
        const float mn0 = fmaxf(mrow0, rm0);
        const float mn1 = fmaxf(mrow1, rm1);
        const float corr0 = __expf(mrow0 - mn0);
        const float corr1 = __expf(mrow1 - mn1);
        float sum0 = 0.f, sum1 = 0.f;
        #pragma unroll
        for (int j = 0; j < 8; ++j) {
            s[j][0] = __expf(s[j][0] - mn0); sum0 += s[j][0];
            s[j][1] = __expf(s[j][1] - mn0); sum0 += s[j][1];
            s[j][2] = __expf(s[j][2] - mn1); sum1 += s[j][2];
            s[j][3] = __expf(s[j][3] - mn1); sum1 += s[j][3];
        }
        sum0 += __shfl_xor_sync(0xffffffffu, sum0, 1);
        sum0 += __shfl_xor_sync(0xffffffffu, sum0, 2);
        sum1 += __shfl_xor_sync(0xffffffffu, sum1, 1);
        sum1 += __shfl_xor_sync(0xffffffffu, sum1, 2);
        lrow0 = lrow0 * corr0 + sum0;
        lrow1 = lrow1 * corr1 + sum1;
        mrow0 = mn0; mrow1 = mn1;
        #pragma unroll
        for (int j = 0; j < 8; ++j) {
            oacc[j][0] *= corr0; oacc[j][1] *= corr0;
            oacc[j][2] *= corr1; oacc[j][3] *= corr1;
        }

        // ---- O += P V
        #pragma unroll
        for (int kk = 0; kk < 4; ++kk) {
            uint32_t ah[4], al[4];
            split2(s[2*kk][0],   s[2*kk][1],   ah[0], al[0]);
            split2(s[2*kk][2],   s[2*kk][3],   ah[1], al[1]);
            split2(s[2*kk+1][0], s[2*kk+1][1], ah[2], al[2]);
            split2(s[2*kk+1][2], s[2*kk+1][3], ah[3], al[3]);
            #pragma unroll
            for (int g = 0; g < 4; ++g) {
                uint32_t vh[4], vl[4];
                uint32_t voff = (uint32_t)(
                    (kk * 16 + ((lane >> 4) << 3) + (lane & 7)) * FS_LD +
                    g * 32 + ((lane >> 3) & 1) * 16);
                ldsm_x4_t(vh, sb + F_VHI + voff);
                ldsm_x4_t(vl, sb + F_VLO + voff);
                #pragma unroll
                for (int od = 0; od < 2; ++od) {
                    const int j = g * 2 + od;
                    mma_bf16(oacc[j], ah[0], ah[1], ah[2], ah[3], vh[od], vh[od + 2]);
                    mma_bf16(oacc[j], ah[0], ah[1], ah[2], ah[3], vl[od], vl[od + 2]);
                    mma_bf16(oacc[j], al[0], al[1], al[2], al[3], vh[od], vh[od + 2]);
                }
            }
        }

        __syncthreads();                    // stage consumed
        if (it + 2 < NT) issueKV(it + 2);   // refill same stage
    }

    // ---- normalize + write context as packed bf16 hi/lo
    const float inv0 = 1.f / lrow0;
    const float inv1 = 1.f / lrow1;
    const int r0 = q0 + w * 16 + (lane >> 2);
    #pragma unroll
    for (int j = 0; j < 8; ++j) {
        const int col = j * 8 + (lane & 3) * 2;
        const size_t i0 = (rbase + r0) * RP + hoff + (col >> 1);
        const size_t i1 = (rbase + r0 + 8) * RP + hoff + (col >> 1);
        uint32_t hh, ll;
        split2(oacc[j][0] * inv0, oacc[j][1] * inv0, hh, ll);
        Ch[i0] = hh; Cl[i0] = ll;
        split2(oacc[j][2] * inv1, oacc[j][3] * inv1, hh, ll);
        Ch[i1] = hh; Cl[i1] = ll;
    }
}

// ---------------------------------------------------------------------------
// Launch
// ---------------------------------------------------------------------------
extern "C" void kernel_launch(void* const* d_in, const int* in_sizes, int n_in,
                              void* d_out, int out_size)
{
    const float* x   = (const float*)d_in[0];
    const int*   am  = (const int*)d_in[1];   // bool mask materialized as int32
    const float* Wq  = (const float*)d_in[2];
    const float* Wk  = (const float*)d_in[3];
    const float* Wv  = (const float*)d_in[4];
    const float* Wo  = (const float*)d_in[5];
    float* out       = (float*)d_out;

    uint32_t *xh, *xl, *wh, *wl, *qkvh, *qkvl, *Chp, *Clp;
    cudaGetSymbolAddress((void**)&xh, g_xh);
    cudaGetSymbolAddress((void**)&xl, g_xl);
    cudaGetSymbolAddress((void**)&wh, g_wh);
    cudaGetSymbolAddress((void**)&wl, g_wl);
    cudaGetSymbolAddress((void**)&qkvh, g_QKVh);
    cudaGetSymbolAddress((void**)&qkvl, g_QKVl);
    cudaGetSymbolAddress((void**)&Chp, g_Ch);
    cudaGetSymbolAddress((void**)&Clp, g_Cl);

    uint32_t* Qh = qkvh;             uint32_t* Ql = qkvl;
    uint32_t* Kh = qkvh + (size_t)N2X;  uint32_t* Kl = qkvl + (size_t)N2X;
    uint32_t* Vh = qkvh + 2 * (size_t)N2X; uint32_t* Vl = qkvl + 2 * (size_t)N2X;

    cudaFuncSetAttribute(gemm_bf, cudaFuncAttributeMaxDynamicSharedMemorySize,
                         GEMM_SMEM);
    cudaFuncSetAttribute(flash_tc, cudaFuncAttributeMaxDynamicSharedMemorySize,
                         FA_SMEM);

    // ---- one fused conversion launch (x + 4 weights), 4-wide
    const int ncvt4 = (N2X + 4 * N2W) / 4;
    cvt_all<<<(ncvt4 + 255) / 256, 256>>>(x, Wq, Wk, Wv, Wo, xh, xl, wh, wl);

    // ---- fused QKV projection: one launch, 3 weight slabs
    dim3 qkv_grid(3 * GN / 128, ROWS / 128);   // (24, 32)
    gemm_bf<<<qkv_grid, 256, GEMM_SMEM>>>(xh, xl, wh, wl, nullptr, qkvh, qkvl);

    dim3 fa_grid(SEQ / 256, HEADS, BATCH);     // (8, 16, 2)
    flash_tc<<<fa_grid, 512, FA_SMEM>>>(Qh, Ql, Kh, Kl, Vh, Vl, am, Chp, Clp);

    // ---- O projection (fp32 out), weight slab 3
    dim3 o_grid(GN / 128, ROWS / 128);         // (8, 32)
    gemm_bf<<<o_grid, 256, GEMM_SMEM>>>(Chp, Clp,
                                        wh + 3 * (size_t)N2W, wl + 3 * (size_t)N2W,
                                        out, nullptr, nullptr);
}

// round 14
// speedup vs baseline: 1.5147x; 1.5147x over previous
#include <cuda_runtime.h>
#include <cuda_bf16.h>
#include <cstdint>

// Problem constants
#define BATCH 2
#define SEQ   2048
#define EMB   1024
#define HEADS 16
#define HDIM  64
#define ROWS  (BATCH * SEQ)   // 4096
#define GK 1024
#define GN 1024
#define RP    (EMB / 2)       // packed uint32 per row = 512
#define N2X   (ROWS * RP)     // 2M
#define N2W   (EMB * RP)      // 512K

// ---------------------------------------------------------------------------
// Scratch: packed bf16x2 hi/lo representations (QKV contiguous)
// ---------------------------------------------------------------------------
__device__ uint32_t g_xh[N2X], g_xl[N2X];
__device__ uint32_t g_wh[4 * N2W], g_wl[4 * N2W];       // Wq,Wk,Wv,Wo
__device__ uint32_t g_QKVh[3 * N2X], g_QKVl[3 * N2X];   // Q,K,V contiguous
__device__ uint32_t g_Ch[N2X], g_Cl[N2X];

// ---------------------------------------------------------------------------
// Helpers
// ---------------------------------------------------------------------------
__device__ __forceinline__ uint32_t smem_to_u32(const void* p) {
    uint32_t a;
    asm("{ .reg .u64 t; cvta.to.shared.u64 t, %1; cvt.u32.u64 %0, t; }"
        : "=r"(a) : "l"(p));
    return a;
}

__device__ __forceinline__ void ldsm_x4(uint32_t r[4], uint32_t addr) {
    asm volatile("ldmatrix.sync.aligned.m8n8.x4.shared.b16 {%0,%1,%2,%3}, [%4];"
                 : "=r"(r[0]), "=r"(r[1]), "=r"(r[2]), "=r"(r[3]) : "r"(addr));
}

__device__ __forceinline__ void ldsm_x4_t(uint32_t r[4], uint32_t addr) {
    asm volatile("ldmatrix.sync.aligned.m8n8.x4.trans.shared.b16 {%0,%1,%2,%3}, [%4];"
                 : "=r"(r[0]), "=r"(r[1]), "=r"(r[2]), "=r"(r[3]) : "r"(addr));
}

__device__ __forceinline__ void mma_bf16(float c[4],
    uint32_t a0, uint32_t a1, uint32_t a2, uint32_t a3,
    uint32_t b0, uint32_t b1)
{
    asm volatile(
        "mma.sync.aligned.m16n8k16.row.col.f32.bf16.bf16.f32 "
        "{%0,%1,%2,%3}, {%4,%5,%6,%7}, {%8,%9}, {%0,%1,%2,%3};"
        : "+f"(c[0]), "+f"(c[1]), "+f"(c[2]), "+f"(c[3])
        : "r"(a0), "r"(a1), "r"(a2), "r"(a3), "r"(b0), "r"(b1));
}

// split fp32 pair -> packed bf16x2 hi (lo16=x, hi16=y) and lo (residuals)
__device__ __forceinline__ void split2(float x, float y, uint32_t& hi, uint32_t& lo)
{
    uint32_t h;
    asm("cvt.rn.bf16x2.f32 %0, %1, %2;" : "=r"(h) : "f"(y), "f"(x));
    float hx = __uint_as_float(h << 16);
    float hy = __uint_as_float(h & 0xffff0000u);
    float lx = x - hx, ly = y - hy;
    uint32_t l;
    asm("cvt.rn.bf16x2.f32 %0, %1, %2;" : "=r"(l) : "f"(ly), "f"(lx));
    hi = h; lo = l;
}

// cp.async
#define CP16(smem, gptr) \
    asm volatile("cp.async.cg.shared.global [%0], [%1], 16;" \
                 :: "r"(smem), "l"(gptr) : "memory")
#define CP4(smem, gptr) \
    asm volatile("cp.async.ca.shared.global [%0], [%1], 4;" \
                 :: "r"(smem), "l"(gptr) : "memory")
#define CP_COMMIT() asm volatile("cp.async.commit_group;" ::: "memory")
#define CP_WAIT0()  asm volatile("cp.async.wait_group 0;" ::: "memory")
#define CP_WAIT1()  asm volatile("cp.async.wait_group 1;" ::: "memory")
#define CP_WAIT2()  asm volatile("cp.async.wait_group 2;" ::: "memory")

// ---------------------------------------------------------------------------
// Fused pre-conversion: x + all 4 weights in ONE launch, 4-wide vectorized
// ---------------------------------------------------------------------------
__global__ void cvt_all(const float* __restrict__ x,
                        const float* __restrict__ Wq, const float* __restrict__ Wk,
                        const float* __restrict__ Wv, const float* __restrict__ Wo,
                        uint32_t* __restrict__ xh, uint32_t* __restrict__ xl,
                        uint32_t* __restrict__ wh, uint32_t* __restrict__ wl)
{
    int q = blockIdx.x * blockDim.x + threadIdx.x;   // quad index (4 uint32 each)
    const int NQX = N2X / 4, NQW = N2W / 4;
    if (q >= NQX + 4 * NQW) return;
    const float* src;
    uint32_t *dh, *dl;
    int j;
    if (q < NQX) {
        src = x; dh = xh; dl = xl; j = q;
    } else {
        int t = (q - NQX) / NQW;
        j = (q - NQX) - t * NQW;
        src = (t == 0) ? Wq : (t == 1) ? Wk : (t == 2) ? Wv : Wo;
        dh = wh + (size_t)t * N2W;
        dl = wl + (size_t)t * N2W;
    }
    float4 v0 = ((const float4*)src)[j * 2];
    float4 v1 = ((const float4*)src)[j * 2 + 1];
    uint4 hi, lo;
    split2(v0.x, v0.y, hi.x, lo.x);
    split2(v0.z, v0.w, hi.y, lo.y);
    split2(v1.x, v1.y, hi.z, lo.z);
    split2(v1.z, v1.w, hi.w, lo.w);
    ((uint4*)dh)[j] = hi;
    ((uint4*)dl)[j] = lo;
}

// ===========================================================================
// HMMA NT GEMM on pre-split bf16 inputs (R10/R12 champion, byte-identical).
// 3-stage cp.async ring, ONE __syncthreads per K-chunk, 2 CTAs/SM.
// Unpadded 64B rows with XOR swizzle: granule' = granule ^ ((row>>1)&3).
// ===========================================================================
#define OFF_AHI 0
#define OFF_ALO 8192
#define OFF_BHI 16384
#define OFF_BLO 24576
#define STAGE_B 32768
#define GEMM_SMEM (3 * STAGE_B)          // 98304 B

#define GSWZ(row, g) ((uint32_t)((row) * 64 + (((g) ^ (((row) >> 1) & 3)) << 4)))

__global__ __launch_bounds__(256, 2) void gemm_bf(
    const uint32_t* __restrict__ Ah, const uint32_t* __restrict__ Al,
    const uint32_t* __restrict__ Bh_base, const uint32_t* __restrict__ Bl_base,
    float* __restrict__ Cf,
    uint32_t* __restrict__ Ch_base, uint32_t* __restrict__ Cl_base)
{
    extern __shared__ char smc[];
    const uint32_t sbase = smem_to_u32(smc);
    const int tid  = threadIdx.x;
    const int lane = tid & 31;
    const int w    = tid >> 5;
    const int wm   = w >> 2;
    const int wn   = w & 3;
    const int mat  = blockIdx.x >> 3;            // 0 for single-mat grids
    const int bn   = (blockIdx.x & 7) * 128;
    const int bm   = blockIdx.y * 128;

    const uint32_t* Bh = Bh_base + (size_t)mat * N2W;
    const uint32_t* Bl = Bl_base + (size_t)mat * N2W;
    uint32_t* Ch = Ch_base ? Ch_base + (size_t)mat * N2X : nullptr;
    uint32_t* Cl = Cl_base ? Cl_base + (size_t)mat * N2X : nullptr;

    float acc[4][4][4];
    #pragma unroll
    for (int i = 0; i < 4; i++)
        #pragma unroll
        for (int j = 0; j < 4; j++)
            #pragma unroll
            for (int q = 0; q < 4; q++) acc[i][j][q] = 0.f;

    // issue one K-chunk c into stage c%3
    auto issue = [&](int c) {
        const uint32_t stg = (uint32_t)(c % 3) * STAGE_B;
        #pragma unroll
        for (int u = 0; u < 8; ++u) {
            const int half = u >> 1;                 // 0:Ah 1:Al 2:Bh 3:Bl
            const int rem  = ((u & 1) << 8) + tid;   // 0..511
            const int row  = rem >> 2;
            const int seg  = rem & 3;
            const int grow = (half < 2 ? bm : bn) + row;
            const uint32_t* gp =
                (half == 0 ? Ah : half == 1 ? Al : half == 2 ? Bh : Bl)
                + (size_t)grow * RP + c * 16 + seg * 4;
            uint32_t sa = sbase + stg + (uint32_t)(half * 8192) + GSWZ(row, seg);
            CP16(sa, gp);
        }
        CP_COMMIT();
    };

    const int NCH = GK / 32;   // 32
    issue(0);
    issue(1);

    for (int it = 0; it < NCH; ++it) {
        if (it < NCH - 1) { CP_WAIT1(); } else { CP_WAIT0(); }
        __syncthreads();
        if (it + 2 < NCH) issue(it + 2);   // stage (it+2)%3 == (it-1)%3, consumed

        const uint32_t sb = sbase + (uint32_t)(it % 3) * STAGE_B;
        #pragma unroll
        for (int ks = 0; ks < 2; ++ks) {
            uint32_t ah[4][4], al[4][4], bh[2][4], bl[2][4];
            const int g = ks * 2 + (lane >> 4);      // granule 0..3
            const int arow = wm * 64 + (lane & 15);
            #pragma unroll
            for (int ms = 0; ms < 4; ++ms) {
                uint32_t off = GSWZ(arow + ms * 16, g);
                ldsm_x4(ah[ms], sb + OFF_AHI + off);
                ldsm_x4(al[ms], sb + OFF_ALO + off);
            }
            const int brow = wn * 32 + (lane & 15);
            #pragma unroll
            for (int pr = 0; pr < 2; ++pr) {
                uint32_t off = GSWZ(brow + pr * 16, g);
                ldsm_x4(bh[pr], sb + OFF_BHI + off);
                ldsm_x4(bl[pr], sb + OFF_BLO + off);
            }
            #pragma unroll
            for (int ms = 0; ms < 4; ++ms)
                #pragma unroll
                for (int ns = 0; ns < 4; ++ns) {
                    const int pr = ns >> 1, od = ns & 1;
                    mma_bf16(acc[ms][ns], ah[ms][0], ah[ms][1], ah[ms][2], ah[ms][3],
                             bh[pr][od], bh[pr][od + 2]);
                    mma_bf16(acc[ms][ns], ah[ms][0], ah[ms][1], ah[ms][2], ah[ms][3],
                             bl[pr][od], bl[pr][od + 2]);
                    mma_bf16(acc[ms][ns], al[ms][0], al[ms][1], al[ms][2], al[ms][3],
                             bh[pr][od], bh[pr][od + 2]);
                }
        }
    }

    // ---- epilogue
    #pragma unroll
    for (int ms = 0; ms < 4; ++ms) {
        const int row0 = bm + wm * 64 + ms * 16 + (lane >> 2);
        #pragma unroll
        for (int ns = 0; ns < 4; ++ns) {
            const int col = bn + wn * 32 + ns * 8 + (lane & 3) * 2;
            if (Cf) {
                *(float2*)&Cf[(size_t)row0 * GN + col] =
                    make_float2(acc[ms][ns][0], acc[ms][ns][1]);
                *(float2*)&Cf[(size_t)(row0 + 8) * GN + col] =
                    make_float2(acc[ms][ns][2], acc[ms][ns][3]);
            } else {
                uint32_t h, l;
                split2(acc[ms][ns][0], acc[ms][ns][1], h, l);
                Ch[(size_t)row0 * RP + (col >> 1)] = h;
                Cl[(size_t)row0 * RP + (col >> 1)] = l;
                split2(acc[ms][ns][2], acc[ms][ns][3], h, l);
                Ch[(size_t)(row0 + 8) * RP + (col >> 1)] = h;
                Cl[(size_t)(row0 + 8) * RP + (col >> 1)] = l;
            }
        }
    }
}

// ===========================================================================
// Tensor-core flash attention (R12 champion, byte-identical).
// 2-stage cp.async KV ring at distance 2, resident Q smem,
// Q-lo fragments reloaded per tile, 2 CTAs/SM.
// ===========================================================================
#define FS_LD    144
#define F_KLO    9216
#define F_VHI    18432
#define F_VLO    27648
#define KV_STG   36864                  // bytes per stage
#define FBIAS    (2 * KV_STG)           // 73728: 2 x 64 ints
#define FQ_HI    (FBIAS + 2 * 256)      // 74240
#define FQ_LO    (FQ_HI + 18432)        // 92672
#define FA_SMEM  (FQ_LO + 18432)        // 111104 B

__global__ __launch_bounds__(256, 2) void flash_tc(
    const uint32_t* __restrict__ Qh_g, const uint32_t* __restrict__ Ql_g,
    const uint32_t* __restrict__ Kh_g, const uint32_t* __restrict__ Kl_g,
    const uint32_t* __restrict__ Vh_g, const uint32_t* __restrict__ Vl_g,
    const int* __restrict__ mask,
    uint32_t* __restrict__ Ch, uint32_t* __restrict__ Cl)
{
    extern __shared__ char smc[];
    const uint32_t sbase = smem_to_u32(smc);
    const int tid  = threadIdx.x;
    const int lane = tid & 31;
    const int w    = tid >> 5;
    const int q0 = blockIdx.x * 128;
    const int h  = blockIdx.y;
    const int b  = blockIdx.z;

    const size_t rbase = (size_t)b * SEQ;
    const int hoff = h * (HDIM / 2);    // packed col offset = h*32
    const int* mb = mask + rbase;

    auto issueKV = [&](int t) {
        const uint32_t stg = (uint32_t)(t & 1) * KV_STG;
        const int kv0 = t * 64;
        #pragma unroll
        for (int u = 0; u < 8; ++u) {
            const int half = u >> 1;                 // 0:Kh 1:Kl 2:Vh 3:Vl
            const int rem  = ((u & 1) << 8) + tid;   // 0..511
            const int row  = rem >> 3;
            const int seg  = rem & 7;
            const uint32_t* gp =
                (half == 0 ? Kh_g : half == 1 ? Kl_g : half == 2 ? Vh_g : Vl_g)
                + (rbase + kv0 + row) * RP + hoff + seg * 4;
            uint32_t sa = sbase + stg + (uint32_t)(half * 9216 + row * FS_LD + seg * 16);
            CP16(sa, gp);
        }
        if (tid < 64)
            CP4(sbase + FBIAS + (uint32_t)((t & 1) * 256 + tid * 4), mb + kv0 + tid);
        CP_COMMIT();
    };

    // ---- issue Q (128 rows x 2 halves), then KV tiles 0,1
    {
        #pragma unroll
        for (int u = 0; u < 8; ++u) {
            const int half = u >> 2;
            const int rem  = ((u & 3) << 8) + tid;   // 0..1023
            const int row  = rem >> 3;
            const int seg  = rem & 7;
            const uint32_t* gp = (half ? Ql_g : Qh_g) +
                (rbase + q0 + row) * RP + hoff + seg * 4;
            uint32_t sa = sbase + (half ? FQ_LO : FQ_HI) +
                          (uint32_t)(row * FS_LD + seg * 16);
            CP16(sa, gp);
        }
        CP_COMMIT();
    }
    issueKV(0);
    issueKV(1);

    CP_WAIT2();          // Q group complete
    __syncthreads();

    // ---- Q-hi fragments register-resident; Q-lo reloaded per tile
    uint32_t qh[4][4];
    #pragma unroll
    for (int ks = 0; ks < 4; ++ks) {
        uint32_t off = (uint32_t)((w * 16 + (lane & 15)) * FS_LD +
                                  (ks * 16 + ((lane >> 4) << 3)) * 2);
        ldsm_x4(qh[ks], sbase + FQ_HI + off);
    }

    float oacc[8][4];
    #pragma unroll
    for (int j = 0; j < 8; ++j)
        #pragma unroll
        for (int q = 0; q < 4; ++q) oacc[j][q] = 0.f;
    float mrow0 = -1e30f, mrow1 = -1e30f, lrow0 = 0.f, lrow1 = 0.f;

    const int NT = SEQ / 64;   // 32

    for (int it = 0; it < NT; ++it) {
        if (it < NT - 1) { CP_WAIT1(); } else { CP_WAIT0(); }
        __syncthreads();

        const int sti = it & 1;
        const uint32_t sb = sbase + (uint32_t)sti * KV_STG;

        // ---- S = Q K^T : split-bf16 3-pass; ks outer so ql is transient
        float s[8][4];
        #pragma unroll
        for (int j = 0; j < 8; ++j)
            #pragma unroll
            for (int q = 0; q < 4; ++q) s[j][q] = 0.f;

        #pragma unroll
        for (int ks = 0; ks < 4; ++ks) {
            uint32_t ql[4];
            uint32_t qoff = (uint32_t)((w * 16 + (lane & 15)) * FS_LD +
                                       (ks * 16 + ((lane >> 4) << 3)) * 2);
            ldsm_x4(ql, sbase + FQ_LO + qoff);
            #pragma unroll
            for (int pr = 0; pr < 4; ++pr) {
                uint32_t kh[4], kl[4];
                uint32_t off = (uint32_t)(((lane & 15) + pr * 16) * FS_LD +
                                          (ks * 16 + ((lane >> 4) << 3)) * 2);
                ldsm_x4(kh, sb + off);
                ldsm_x4(kl, sb + F_KLO + off);
                #pragma unroll
                for (int od = 0; od < 2; ++od) {
                    const int j = pr * 2 + od;
                    mma_bf16(s[j], qh[ks][0], qh[ks][1], qh[ks][2], qh[ks][3],
                             kh[od], kh[od + 2]);
                    mma_bf16(s[j], qh[ks][0], qh[ks][1], qh[ks][2], qh[ks][3],
                             kl[od], kl[od + 2]);
                    mma_bf16(s[j], ql[0], ql[1], ql[2], ql[3],
                             kh[od], kh[od + 2]);
                }
            }
        }

        // ---- scale + mask bias
        const float scale = 0.125f;   // 1/sqrt(64)
        #pragma unroll
        for (int j = 0; j < 8; ++j) {
            int2 mm = *(int2*)(smc + FBIAS + sti * 256 +
                               (j * 8 + (lane & 3) * 2) * 4);
            const float bx = mm.x ? 0.f : -1e30f;
            const float by = mm.y ? 0.f : -1e30f;
            s[j][0] = s[j][0] * scale + bx;
            s[j][1] = s[j][1] * scale + by;
            s[j][2] = s[j][2] * scale + bx;
            s[j][3] = s[j][3] * scale + by;
        }

        // ---- online softmax (rows on quads: shfl_xor 1,2)
        float rm0 = -1e30f, rm1 = -1e30f;
        #pragma unroll
        for (int j = 0; j < 8; ++j) {
            rm0 = fmaxf(rm0, fmaxf(s[j][0], s[j][1]));
            rm1 = fmaxf(rm1, fmaxf(s[j][2], s[j][3]));
        }
        rm0 = fmaxf(rm0, __shfl_xor_sync(0xffffffffu, rm0, 1));
        rm0 = fmaxf(rm0, __shfl_xor_sync(0xffffffffu, rm0, 2));
        rm1 = fmaxf(rm1, __shfl_xor_sync(0xffffffffu, rm1, 1));
        rm1 = fmaxf(rm1, __shfl_xor_sync(0xffffffffu, rm1, 2));
        const float mn0 = fmaxf(mrow0, rm0);
        const float mn1 = fmaxf(mrow1, rm1);
        const float corr0 = __expf(mrow0 - mn0);
        const float corr1 = __expf(mrow1 - mn1);
        float sum0 = 0.f, sum1 = 0.f;
        #pragma unroll
        for (int j = 0; j < 8; ++j) {
            s[j][0] = __expf(s[j][0] - mn0); sum0 += s[j][0];
            s[j][1] = __expf(s[j][1] - mn0); sum0 += s[j][1];
            s[j][2] = __expf(s[j][2] - mn1); sum1 += s[j][2];
            s[j][3] = __expf(s[j][3] - mn1); sum1 += s[j][3];
        }
        sum0 += __shfl_xor_sync(0xffffffffu, sum0, 1);
        sum0 += __shfl_xor_sync(0xffffffffu, sum0, 2);
        sum1 += __shfl_xor_sync(0xffffffffu, sum1, 1);
        sum1 += __shfl_xor_sync(0xffffffffu, sum1, 2);
        lrow0 = lrow0 * corr0 + sum0;
        lrow1 = lrow1 * corr1 + sum1;
        mrow0 = mn0; mrow1 = mn1;
        #pragma unroll
        for (int j = 0; j < 8; ++j) {
            oacc[j][0] *= corr0; oacc[j][1] *= corr0;
            oacc[j][2] *= corr1; oacc[j][3] *= corr1;
        }

        // ---- O += P V
        #pragma unroll
        for (int kk = 0; kk < 4; ++kk) {
            uint32_t ah[4], al[4];
            split2(s[2*kk][0],   s[2*kk][1],   ah[0], al[0]);
            split2(s[2*kk][2],   s[2*kk][3],   ah[1], al[1]);
            split2(s[2*kk+1][0], s[2*kk+1][1], ah[2], al[2]);
            split2(s[2*kk+1][2], s[2*kk+1][3], ah[3], al[3]);
            #pragma unroll
            for (int g = 0; g < 4; ++g) {
                uint32_t vh[4], vl[4];
                uint32_t voff = (uint32_t)(
                    (kk * 16 + ((lane >> 4) << 3) + (lane & 7)) * FS_LD +
                    g * 32 + ((lane >> 3) & 1) * 16);
                ldsm_x4_t(vh, sb + F_VHI + voff);
                ldsm_x4_t(vl, sb + F_VLO + voff);
                #pragma unroll
                for (int od = 0; od < 2; ++od) {
                    const int j = g * 2 + od;
                    mma_bf16(oacc[j], ah[0], ah[1], ah[2], ah[3], vh[od], vh[od + 2]);
                    mma_bf16(oacc[j], ah[0], ah[1], ah[2], ah[3], vl[od], vl[od + 2]);
                    mma_bf16(oacc[j], al[0], al[1], al[2], al[3], vh[od], vh[od + 2]);
                }
            }
        }

        __syncthreads();                    // stage consumed
        if (it + 2 < NT) issueKV(it + 2);   // refill same stage
    }

    // ---- normalize + write context as packed bf16 hi/lo
    const float inv0 = 1.f / lrow0;
    const float inv1 = 1.f / lrow1;
    const int r0 = q0 + w * 16 + (lane >> 2);
    #pragma unroll
    for (int j = 0; j < 8; ++j) {
        const int col = j * 8 + (lane & 3) * 2;
        const size_t i0 = (rbase + r0) * RP + hoff + (col >> 1);
        const size_t i1 = (rbase + r0 + 8) * RP + hoff + (col >> 1);
        uint32_t hh, ll;
        split2(oacc[j][0] * inv0, oacc[j][1] * inv0, hh, ll);
        Ch[i0] = hh; Cl[i0] = ll;
        split2(oacc[j][2] * inv1, oacc[j][3] * inv1, hh, ll);
        Ch[i1] = hh; Cl[i1] = ll;
    }
}

// ---------------------------------------------------------------------------
// Launch
// ---------------------------------------------------------------------------
extern "C" void kernel_launch(void* const* d_in, const int* in_sizes, int n_in,
                              void* d_out, int out_size)
{
    const float* x   = (const float*)d_in[0];
    const int*   am  = (const int*)d_in[1];   // bool mask materialized as int32
    const float* Wq  = (const float*)d_in[2];
    const float* Wk  = (const float*)d_in[3];
    const float* Wv  = (const float*)d_in[4];
    const float* Wo  = (const float*)d_in[5];
    float* out       = (float*)d_out;

    uint32_t *xh, *xl, *wh, *wl, *qkvh, *qkvl, *Chp, *Clp;
    cudaGetSymbolAddress((void**)&xh, g_xh);
    cudaGetSymbolAddress((void**)&xl, g_xl);
    cudaGetSymbolAddress((void**)&wh, g_wh);
    cudaGetSymbolAddress((void**)&wl, g_wl);
    cudaGetSymbolAddress((void**)&qkvh, g_QKVh);
    cudaGetSymbolAddress((void**)&qkvl, g_QKVl);
    cudaGetSymbolAddress((void**)&Chp, g_Ch);
    cudaGetSymbolAddress((void**)&Clp, g_Cl);

    uint32_t* Qh = qkvh;             uint32_t* Ql = qkvl;
    uint32_t* Kh = qkvh + (size_t)N2X;  uint32_t* Kl = qkvl + (size_t)N2X;
    uint32_t* Vh = qkvh + 2 * (size_t)N2X; uint32_t* Vl = qkvl + 2 * (size_t)N2X;

    cudaFuncSetAttribute(gemm_bf, cudaFuncAttributeMaxDynamicSharedMemorySize,
                         GEMM_SMEM);
    cudaFuncSetAttribute(flash_tc, cudaFuncAttributeMaxDynamicSharedMemorySize,
                         FA_SMEM);

    // ---- one fused conversion launch (x + 4 weights), 4-wide
    const int ncvt4 = (N2X + 4 * N2W) / 4;
    cvt_all<<<(ncvt4 + 255) / 256, 256>>>(x, Wq, Wk, Wv, Wo, xh, xl, wh, wl);

    // ---- fused QKV projection: one launch, 3 weight slabs
    dim3 qkv_grid(3 * GN / 128, ROWS / 128);   // (24, 32)
    gemm_bf<<<qkv_grid, 256, GEMM_SMEM>>>(xh, xl, wh, wl, nullptr, qkvh, qkvl);

    dim3 fa_grid(SEQ / 128, HEADS, BATCH);     // (16, 16, 2)
    flash_tc<<<fa_grid, 256, FA_SMEM>>>(Qh, Ql, Kh, Kl, Vh, Vl, am, Chp, Clp);

    // ---- O projection (fp32 out), weight slab 3
    dim3 o_grid(GN / 128, ROWS / 128);         // (8, 32)
    gemm_bf<<<o_grid, 256, GEMM_SMEM>>>(Chp, Clp,
                                        wh + 3 * (size_t)N2W, wl + 3 * (size_t)N2W,
                                        out, nullptr, nullptr);
}

// round 15
// speedup vs baseline: 1.5331x; 1.0122x over previous
#include <cuda_runtime.h>
#include <cuda_bf16.h>
#include <cstdint>

// Problem constants
#define BATCH 2
#define SEQ   2048
#define EMB   1024
#define HEADS 16
#define HDIM  64
#define ROWS  (BATCH * SEQ)   // 4096
#define GK 1024
#define GN 1024
#define RP    (EMB / 2)       // packed uint32 per row = 512
#define N2X   (ROWS * RP)     // 2M
#define N2W   (EMB * RP)      // 512K

// ---------------------------------------------------------------------------
// Scratch: packed bf16x2 hi/lo representations (QKV contiguous)
// ---------------------------------------------------------------------------
__device__ uint32_t g_xh[N2X], g_xl[N2X];
__device__ uint32_t g_wh[4 * N2W], g_wl[4 * N2W];       // Wq,Wk,Wv,Wo
__device__ uint32_t g_QKVh[3 * N2X], g_QKVl[3 * N2X];   // Q,K,V contiguous
__device__ uint32_t g_Ch[N2X], g_Cl[N2X];

// ---------------------------------------------------------------------------
// Helpers
// ---------------------------------------------------------------------------
__device__ __forceinline__ uint32_t smem_to_u32(const void* p) {
    uint32_t a;
    asm("{ .reg .u64 t; cvta.to.shared.u64 t, %1; cvt.u32.u64 %0, t; }"
        : "=r"(a) : "l"(p));
    return a;
}

__device__ __forceinline__ void ldsm_x4(uint32_t r[4], uint32_t addr) {
    asm volatile("ldmatrix.sync.aligned.m8n8.x4.shared.b16 {%0,%1,%2,%3}, [%4];"
                 : "=r"(r[0]), "=r"(r[1]), "=r"(r[2]), "=r"(r[3]) : "r"(addr));
}

__device__ __forceinline__ void ldsm_x4_t(uint32_t r[4], uint32_t addr) {
    asm volatile("ldmatrix.sync.aligned.m8n8.x4.trans.shared.b16 {%0,%1,%2,%3}, [%4];"
                 : "=r"(r[0]), "=r"(r[1]), "=r"(r[2]), "=r"(r[3]) : "r"(addr));
}

__device__ __forceinline__ void mma_bf16(float c[4],
    uint32_t a0, uint32_t a1, uint32_t a2, uint32_t a3,
    uint32_t b0, uint32_t b1)
{
    asm volatile(
        "mma.sync.aligned.m16n8k16.row.col.f32.bf16.bf16.f32 "
        "{%0,%1,%2,%3}, {%4,%5,%6,%7}, {%8,%9}, {%0,%1,%2,%3};"
        : "+f"(c[0]), "+f"(c[1]), "+f"(c[2]), "+f"(c[3])
        : "r"(a0), "r"(a1), "r"(a2), "r"(a3), "r"(b0), "r"(b1));
}

// split fp32 pair -> packed bf16x2 hi (lo16=x, hi16=y) and lo (residuals)
__device__ __forceinline__ void split2(float x, float y, uint32_t& hi, uint32_t& lo)
{
    uint32_t h;
    asm("cvt.rn.bf16x2.f32 %0, %1, %2;" : "=r"(h) : "f"(y), "f"(x));
    float hx = __uint_as_float(h << 16);
    float hy = __uint_as_float(h & 0xffff0000u);
    float lx = x - hx, ly = y - hy;
    uint32_t l;
    asm("cvt.rn.bf16x2.f32 %0, %1, %2;" : "=r"(l) : "f"(ly), "f"(lx));
    hi = h; lo = l;
}

// cp.async
#define CP16(smem, gptr) \
    asm volatile("cp.async.cg.shared.global [%0], [%1], 16;" \
                 :: "r"(smem), "l"(gptr) : "memory")
#define CP4(smem, gptr) \
    asm volatile("cp.async.ca.shared.global [%0], [%1], 4;" \
                 :: "r"(smem), "l"(gptr) : "memory")
#define CP_COMMIT() asm volatile("cp.async.commit_group;" ::: "memory")
#define CP_WAIT0()  asm volatile("cp.async.wait_group 0;" ::: "memory")
#define CP_WAIT1()  asm volatile("cp.async.wait_group 1;" ::: "memory")
#define CP_WAIT2()  asm volatile("cp.async.wait_group 2;" ::: "memory")

// ---------------------------------------------------------------------------
// Fused pre-conversion: x + all 4 weights in ONE launch, 4-wide vectorized
// ---------------------------------------------------------------------------
__global__ void cvt_all(const float* __restrict__ x,
                        const float* __restrict__ Wq, const float* __restrict__ Wk,
                        const float* __restrict__ Wv, const float* __restrict__ Wo,
                        uint32_t* __restrict__ xh, uint32_t* __restrict__ xl,
                        uint32_t* __restrict__ wh, uint32_t* __restrict__ wl)
{
    int q = blockIdx.x * blockDim.x + threadIdx.x;   // quad index (4 uint32 each)
    const int NQX = N2X / 4, NQW = N2W / 4;
    if (q >= NQX + 4 * NQW) return;
    const float* src;
    uint32_t *dh, *dl;
    int j;
    if (q < NQX) {
        src = x; dh = xh; dl = xl; j = q;
    } else {
        int t = (q - NQX) / NQW;
        j = (q - NQX) - t * NQW;
        src = (t == 0) ? Wq : (t == 1) ? Wk : (t == 2) ? Wv : Wo;
        dh = wh + (size_t)t * N2W;
        dl = wl + (size_t)t * N2W;
    }
    float4 v0 = ((const float4*)src)[j * 2];
    float4 v1 = ((const float4*)src)[j * 2 + 1];
    uint4 hi, lo;
    split2(v0.x, v0.y, hi.x, lo.x);
    split2(v0.z, v0.w, hi.y, lo.y);
    split2(v1.x, v1.y, hi.z, lo.z);
    split2(v1.z, v1.w, hi.w, lo.w);
    ((uint4*)dh)[j] = hi;
    ((uint4*)dl)[j] = lo;
}

// ===========================================================================
// HMMA NT GEMM on pre-split bf16 inputs. Identical structure to champion,
// EXCEPT: MMA issue order is pass-outermost (all hh, all hl, all lh) so
// same-accumulator MMAs are 16 apart instead of adjacent.
// ===========================================================================
#define OFF_AHI 0
#define OFF_ALO 8192
#define OFF_BHI 16384
#define OFF_BLO 24576
#define STAGE_B 32768
#define GEMM_SMEM (3 * STAGE_B)          // 98304 B

#define GSWZ(row, g) ((uint32_t)((row) * 64 + (((g) ^ (((row) >> 1) & 3)) << 4)))

__global__ __launch_bounds__(256, 2) void gemm_bf(
    const uint32_t* __restrict__ Ah, const uint32_t* __restrict__ Al,
    const uint32_t* __restrict__ Bh_base, const uint32_t* __restrict__ Bl_base,
    float* __restrict__ Cf,
    uint32_t* __restrict__ Ch_base, uint32_t* __restrict__ Cl_base)
{
    extern __shared__ char smc[];
    const uint32_t sbase = smem_to_u32(smc);
    const int tid  = threadIdx.x;
    const int lane = tid & 31;
    const int w    = tid >> 5;
    const int wm   = w >> 2;
    const int wn   = w & 3;
    const int mat  = blockIdx.x >> 3;            // 0 for single-mat grids
    const int bn   = (blockIdx.x & 7) * 128;
    const int bm   = blockIdx.y * 128;

    const uint32_t* Bh = Bh_base + (size_t)mat * N2W;
    const uint32_t* Bl = Bl_base + (size_t)mat * N2W;
    uint32_t* Ch = Ch_base ? Ch_base + (size_t)mat * N2X : nullptr;
    uint32_t* Cl = Cl_base ? Cl_base + (size_t)mat * N2X : nullptr;

    float acc[4][4][4];
    #pragma unroll
    for (int i = 0; i < 4; i++)
        #pragma unroll
        for (int j = 0; j < 4; j++)
            #pragma unroll
            for (int q = 0; q < 4; q++) acc[i][j][q] = 0.f;

    // issue one K-chunk c into stage c%3
    auto issue = [&](int c) {
        const uint32_t stg = (uint32_t)(c % 3) * STAGE_B;
        #pragma unroll
        for (int u = 0; u < 8; ++u) {
            const int half = u >> 1;                 // 0:Ah 1:Al 2:Bh 3:Bl
            const int rem  = ((u & 1) << 8) + tid;   // 0..511
            const int row  = rem >> 2;
            const int seg  = rem & 3;
            const int grow = (half < 2 ? bm : bn) + row;
            const uint32_t* gp =
                (half == 0 ? Ah : half == 1 ? Al : half == 2 ? Bh : Bl)
                + (size_t)grow * RP + c * 16 + seg * 4;
            uint32_t sa = sbase + stg + (uint32_t)(half * 8192) + GSWZ(row, seg);
            CP16(sa, gp);
        }
        CP_COMMIT();
    };

    const int NCH = GK / 32;   // 32
    issue(0);
    issue(1);

    for (int it = 0; it < NCH; ++it) {
        if (it < NCH - 1) { CP_WAIT1(); } else { CP_WAIT0(); }
        __syncthreads();
        if (it + 2 < NCH) issue(it + 2);   // stage (it+2)%3 == (it-1)%3, consumed

        const uint32_t sb = sbase + (uint32_t)(it % 3) * STAGE_B;
        #pragma unroll
        for (int ks = 0; ks < 2; ++ks) {
            uint32_t ah[4][4], al[4][4], bh[2][4], bl[2][4];
            const int g = ks * 2 + (lane >> 4);      // granule 0..3
            const int arow = wm * 64 + (lane & 15);
            #pragma unroll
            for (int ms = 0; ms < 4; ++ms) {
                uint32_t off = GSWZ(arow + ms * 16, g);
                ldsm_x4(ah[ms], sb + OFF_AHI + off);
                ldsm_x4(al[ms], sb + OFF_ALO + off);
            }
            const int brow = wn * 32 + (lane & 15);
            #pragma unroll
            for (int pr = 0; pr < 2; ++pr) {
                uint32_t off = GSWZ(brow + pr * 16, g);
                ldsm_x4(bh[pr], sb + OFF_BHI + off);
                ldsm_x4(bl[pr], sb + OFF_BLO + off);
            }
            // pass-outermost MMA order: same-acc distance = 16
            #pragma unroll
            for (int p = 0; p < 3; ++p)
                #pragma unroll
                for (int ms = 0; ms < 4; ++ms)
                    #pragma unroll
                    for (int ns = 0; ns < 4; ++ns) {
                        const int pr = ns >> 1, od = ns & 1;
                        if (p == 0)
                            mma_bf16(acc[ms][ns],
                                     ah[ms][0], ah[ms][1], ah[ms][2], ah[ms][3],
                                     bh[pr][od], bh[pr][od + 2]);
                        else if (p == 1)
                            mma_bf16(acc[ms][ns],
                                     ah[ms][0], ah[ms][1], ah[ms][2], ah[ms][3],
                                     bl[pr][od], bl[pr][od + 2]);
                        else
                            mma_bf16(acc[ms][ns],
                                     al[ms][0], al[ms][1], al[ms][2], al[ms][3],
                                     bh[pr][od], bh[pr][od + 2]);
                    }
        }
    }

    // ---- epilogue
    #pragma unroll
    for (int ms = 0; ms < 4; ++ms) {
        const int row0 = bm + wm * 64 + ms * 16 + (lane >> 2);
        #pragma unroll
        for (int ns = 0; ns < 4; ++ns) {
            const int col = bn + wn * 32 + ns * 8 + (lane & 3) * 2;
            if (Cf) {
                *(float2*)&Cf[(size_t)row0 * GN + col] =
                    make_float2(acc[ms][ns][0], acc[ms][ns][1]);
                *(float2*)&Cf[(size_t)(row0 + 8) * GN + col] =
                    make_float2(acc[ms][ns][2], acc[ms][ns][3]);
            } else {
                uint32_t h, l;
                split2(acc[ms][ns][0], acc[ms][ns][1], h, l);
                Ch[(size_t)row0 * RP + (col >> 1)] = h;
                Cl[(size_t)row0 * RP + (col >> 1)] = l;
                split2(acc[ms][ns][2], acc[ms][ns][3], h, l);
                Ch[(size_t)(row0 + 8) * RP + (col >> 1)] = h;
                Cl[(size_t)(row0 + 8) * RP + (col >> 1)] = l;
            }
        }
    }
}

// ===========================================================================
// Tensor-core flash attention. Identical structure to champion, EXCEPT:
// QK and PV MMA issue order is pass-outermost within each od-pair
// (same-accumulator distance 1 -> 2).
// ===========================================================================
#define FS_LD    144
#define F_KLO    9216
#define F_VHI    18432
#define F_VLO    27648
#define KV_STG   36864                  // bytes per stage
#define FBIAS    (2 * KV_STG)           // 73728: 2 x 64 ints
#define FQ_HI    (FBIAS + 2 * 256)      // 74240
#define FQ_LO    (FQ_HI + 18432)        // 92672
#define FA_SMEM  (FQ_LO + 18432)        // 111104 B

__global__ __launch_bounds__(256, 2) void flash_tc(
    const uint32_t* __restrict__ Qh_g, const uint32_t* __restrict__ Ql_g,
    const uint32_t* __restrict__ Kh_g, const uint32_t* __restrict__ Kl_g,
    const uint32_t* __restrict__ Vh_g, const uint32_t* __restrict__ Vl_g,
    const int* __restrict__ mask,
    uint32_t* __restrict__ Ch, uint32_t* __restrict__ Cl)
{
    extern __shared__ char smc[];
    const uint32_t sbase = smem_to_u32(smc);
    const int tid  = threadIdx.x;
    const int lane = tid & 31;
    const int w    = tid >> 5;
    const int q0 = blockIdx.x * 128;
    const int h  = blockIdx.y;
    const int b  = blockIdx.z;

    const size_t rbase = (size_t)b * SEQ;
    const int hoff = h * (HDIM / 2);    // packed col offset = h*32
    const int* mb = mask + rbase;

    auto issueKV = [&](int t) {
        const uint32_t stg = (uint32_t)(t & 1) * KV_STG;
        const int kv0 = t * 64;
        #pragma unroll
        for (int u = 0; u < 8; ++u) {
            const int half = u >> 1;                 // 0:Kh 1:Kl 2:Vh 3:Vl
            const int rem  = ((u & 1) << 8) + tid;   // 0..511
            const int row  = rem >> 3;
            const int seg  = rem & 7;
            const uint32_t* gp =
                (half == 0 ? Kh_g : half == 1 ? Kl_g : half == 2 ? Vh_g : Vl_g)
                + (rbase + kv0 + row) * RP + hoff + seg * 4;
            uint32_t sa = sbase + stg + (uint32_t)(half * 9216 + row * FS_LD + seg * 16);
            CP16(sa, gp);
        }
        if (tid < 64)
            CP4(sbase + FBIAS + (uint32_t)((t & 1) * 256 + tid * 4), mb + kv0 + tid);
        CP_COMMIT();
    };

    // ---- issue Q (128 rows x 2 halves), then KV tiles 0,1
    {
        #pragma unroll
        for (int u = 0; u < 8; ++u) {
            const int half = u >> 2;
            const int rem  = ((u & 3) << 8) + tid;   // 0..1023
            const int row  = rem >> 3;
            const int seg  = rem & 7;
            const uint32_t* gp = (half ? Ql_g : Qh_g) +
                (rbase + q0 + row) * RP + hoff + seg * 4;
            uint32_t sa = sbase + (half ? FQ_LO : FQ_HI) +
                          (uint32_t)(row * FS_LD + seg * 16);
            CP16(sa, gp);
        }
        CP_COMMIT();
    }
    issueKV(0);
    issueKV(1);

    CP_WAIT2();          // Q group complete
    __syncthreads();

    // ---- Q-hi fragments register-resident; Q-lo reloaded per tile
    uint32_t qh[4][4];
    #pragma unroll
    for (int ks = 0; ks < 4; ++ks) {
        uint32_t off = (uint32_t)((w * 16 + (lane & 15)) * FS_LD +
                                  (ks * 16 + ((lane >> 4) << 3)) * 2);
        ldsm_x4(qh[ks], sbase + FQ_HI + off);
    }

    float oacc[8][4];
    #pragma unroll
    for (int j = 0; j < 8; ++j)
        #pragma unroll
        for (int q = 0; q < 4; ++q) oacc[j][q] = 0.f;
    float mrow0 = -1e30f, mrow1 = -1e30f, lrow0 = 0.f, lrow1 = 0.f;

    const int NT = SEQ / 64;   // 32

    for (int it = 0; it < NT; ++it) {
        if (it < NT - 1) { CP_WAIT1(); } else { CP_WAIT0(); }
        __syncthreads();

        const int sti = it & 1;
        const uint32_t sb = sbase + (uint32_t)sti * KV_STG;

        // ---- S = Q K^T : split-bf16 3-pass; pass-outer within od-pair
        float s[8][4];
        #pragma unroll
        for (int j = 0; j < 8; ++j)
            #pragma unroll
            for (int q = 0; q < 4; ++q) s[j][q] = 0.f;

        #pragma unroll
        for (int ks = 0; ks < 4; ++ks) {
            uint32_t ql[4];
            uint32_t qoff = (uint32_t)((w * 16 + (lane & 15)) * FS_LD +
                                       (ks * 16 + ((lane >> 4) << 3)) * 2);
            ldsm_x4(ql, sbase + FQ_LO + qoff);
            #pragma unroll
            for (int pr = 0; pr < 4; ++pr) {
                uint32_t kh[4], kl[4];
                uint32_t off = (uint32_t)(((lane & 15) + pr * 16) * FS_LD +
                                          (ks * 16 + ((lane >> 4) << 3)) * 2);
                ldsm_x4(kh, sb + off);
                ldsm_x4(kl, sb + F_KLO + off);
                #pragma unroll
                for (int p = 0; p < 3; ++p)
                    #pragma unroll
                    for (int od = 0; od < 2; ++od) {
                        const int j = pr * 2 + od;
                        if (p == 0)
                            mma_bf16(s[j], qh[ks][0], qh[ks][1], qh[ks][2], qh[ks][3],
                                     kh[od], kh[od + 2]);
                        else if (p == 1)
                            mma_bf16(s[j], qh[ks][0], qh[ks][1], qh[ks][2], qh[ks][3],
                                     kl[od], kl[od + 2]);
                        else
                            mma_bf16(s[j], ql[0], ql[1], ql[2], ql[3],
                                     kh[od], kh[od + 2]);
                    }
            }
        }

        // ---- scale + mask bias
        const float scale = 0.125f;   // 1/sqrt(64)
        #pragma unroll
        for (int j = 0; j < 8; ++j) {
            int2 mm = *(int2*)(smc + FBIAS + sti * 256 +
                               (j * 8 + (lane & 3) * 2) * 4);
            const float bx = mm.x ? 0.f : -1e30f;
            const float by = mm.y ? 0.f : -1e30f;
            s[j][0] = s[j][0] * scale + bx;
            s[j][1] = s[j][1] * scale + by;
            s[j][2] = s[j][2] * scale + bx;
            s[j][3] = s[j][3] * scale + by;
        }

        // ---- online softmax (rows on quads: shfl_xor 1,2)
        float rm0 = -1e30f, rm1 = -1e30f;
        #pragma unroll
        for (int j = 0; j < 8; ++j) {
            rm0 = fmaxf(rm0, fmaxf(s[j][0], s[j][1]));
            rm1 = fmaxf(rm1, fmaxf(s[j][2], s[j][3]));
        }
        rm0 = fmaxf(rm0, __shfl_xor_sync(0xffffffffu, rm0, 1));
        rm0 = fmaxf(rm0, __shfl_xor_sync(0xffffffffu, rm0, 2));
        rm1 = fmaxf(rm1, __shfl_xor_sync(0xffffffffu, rm1, 1));
        rm1 = fmaxf(rm1, __shfl_xor_sync(0xffffffffu, rm1, 2));
        const float mn0 = fmaxf(mrow0, rm0);
        const float mn1 = fmaxf(mrow1, rm1);
        const float corr0 = __expf(mrow0 - mn0);
        const float corr1 = __expf(mrow1 - mn1);
        float sum0 = 0.f, sum1 = 0.f;
        #pragma unroll
        for (int j = 0; j < 8; ++j) {
            s[j][0] = __expf(s[j][0] - mn0); sum0 += s[j][0];
            s[j][1] = __expf(s[j][1] - mn0); sum0 += s[j][1];
            s[j][2] = __expf(s[j][2] - mn1); sum1 += s[j][2];
            s[j][3] = __expf(s[j][3] - mn1); sum1 += s[j][3];
        }
        sum0 += __shfl_xor_sync(0xffffffffu, sum0, 1);
        sum0 += __shfl_xor_sync(0xffffffffu, sum0, 2);
        sum1 += __shfl_xor_sync(0xffffffffu, sum1, 1);
        sum1 += __shfl_xor_sync(0xffffffffu, sum1, 2);
        lrow0 = lrow0 * corr0 + sum0;
        lrow1 = lrow1 * corr1 + sum1;
        mrow0 = mn0; mrow1 = mn1;
        #pragma unroll
        for (int j = 0; j < 8; ++j) {
            oacc[j][0] *= corr0; oacc[j][1] *= corr0;
            oacc[j][2] *= corr1; oacc[j][3] *= corr1;
        }

        // ---- O += P V : pass-outer within od-pair
        #pragma unroll
        for (int kk = 0; kk < 4; ++kk) {
            uint32_t ah[4], al[4];
            split2(s[2*kk][0],   s[2*kk][1],   ah[0], al[0]);
            split2(s[2*kk][2],   s[2*kk][3],   ah[1], al[1]);
            split2(s[2*kk+1][0], s[2*kk+1][1], ah[2], al[2]);
            split2(s[2*kk+1][2], s[2*kk+1][3], ah[3], al[3]);
            #pragma unroll
            for (int g = 0; g < 4; ++g) {
                uint32_t vh[4], vl[4];
                uint32_t voff = (uint32_t)(
                    (kk * 16 + ((lane >> 4) << 3) + (lane & 7)) * FS_LD +
                    g * 32 + ((lane >> 3) & 1) * 16);
                ldsm_x4_t(vh, sb + F_VHI + voff);
                ldsm_x4_t(vl, sb + F_VLO + voff);
                #pragma unroll
                for (int p = 0; p < 3; ++p)
                    #pragma unroll
                    for (int od = 0; od < 2; ++od) {
                        const int j = g * 2 + od;
                        if (p == 0)
                            mma_bf16(oacc[j], ah[0], ah[1], ah[2], ah[3],
                                     vh[od], vh[od + 2]);
                        else if (p == 1)
                            mma_bf16(oacc[j], ah[0], ah[1], ah[2], ah[3],
                                     vl[od], vl[od + 2]);
                        else
                            mma_bf16(oacc[j], al[0], al[1], al[2], al[3],
                                     vh[od], vh[od + 2]);
                    }
            }
        }

        __syncthreads();                    // stage consumed
        if (it + 2 < NT) issueKV(it + 2);   // refill same stage
    }

    // ---- normalize + write context as packed bf16 hi/lo
    const float inv0 = 1.f / lrow0;
    const float inv1 = 1.f / lrow1;
    const int r0 = q0 + w * 16 + (lane >> 2);
    #pragma unroll
    for (int j = 0; j < 8; ++j) {
        const int col = j * 8 + (lane & 3) * 2;
        const size_t i0 = (rbase + r0) * RP + hoff + (col >> 1);
        const size_t i1 = (rbase + r0 + 8) * RP + hoff + (col >> 1);
        uint32_t hh, ll;
        split2(oacc[j][0] * inv0, oacc[j][1] * inv0, hh, ll);
        Ch[i0] = hh; Cl[i0] = ll;
        split2(oacc[j][2] * inv1, oacc[j][3] * inv1, hh, ll);
        Ch[i1] = hh; Cl[i1] = ll;
    }
}

// ---------------------------------------------------------------------------
// Launch
// ---------------------------------------------------------------------------
extern "C" void kernel_launch(void* const* d_in, const int* in_sizes, int n_in,
                              void* d_out, int out_size)
{
    const float* x   = (const float*)d_in[0];
    const int*   am  = (const int*)d_in[1];   // bool mask materialized as int32
    const float* Wq  = (const float*)d_in[2];
    const float* Wk  = (const float*)d_in[3];
    const float* Wv  = (const float*)d_in[4];
    const float* Wo  = (const float*)d_in[5];
    float* out       = (float*)d_out;

    uint32_t *xh, *xl, *wh, *wl, *qkvh, *qkvl, *Chp, *Clp;
    cudaGetSymbolAddress((void**)&xh, g_xh);
    cudaGetSymbolAddress((void**)&xl, g_xl);
    cudaGetSymbolAddress((void**)&wh, g_wh);
    cudaGetSymbolAddress((void**)&wl, g_wl);
    cudaGetSymbolAddress((void**)&qkvh, g_QKVh);
    cudaGetSymbolAddress((void**)&qkvl, g_QKVl);
    cudaGetSymbolAddress((void**)&Chp, g_Ch);
    cudaGetSymbolAddress((void**)&Clp, g_Cl);

    uint32_t* Qh = qkvh;             uint32_t* Ql = qkvl;
    uint32_t* Kh = qkvh + (size_t)N2X;  uint32_t* Kl = qkvl + (size_t)N2X;
    uint32_t* Vh = qkvh + 2 * (size_t)N2X; uint32_t* Vl = qkvl + 2 * (size_t)N2X;

    cudaFuncSetAttribute(gemm_bf, cudaFuncAttributeMaxDynamicSharedMemorySize,
                         GEMM_SMEM);
    cudaFuncSetAttribute(flash_tc, cudaFuncAttributeMaxDynamicSharedMemorySize,
                         FA_SMEM);

    // ---- one fused conversion launch (x + 4 weights), 4-wide
    const int ncvt4 = (N2X + 4 * N2W) / 4;
    cvt_all<<<(ncvt4 + 255) / 256, 256>>>(x, Wq, Wk, Wv, Wo, xh, xl, wh, wl);

    // ---- fused QKV projection: one launch, 3 weight slabs
    dim3 qkv_grid(3 * GN / 128, ROWS / 128);   // (24, 32)
    gemm_bf<<<qkv_grid, 256, GEMM_SMEM>>>(xh, xl, wh, wl, nullptr, qkvh, qkvl);

    dim3 fa_grid(SEQ / 128, HEADS, BATCH);     // (16, 16, 2)
    flash_tc<<<fa_grid, 256, FA_SMEM>>>(Qh, Ql, Kh, Kl, Vh, Vl, am, Chp, Clp);

    // ---- O projection (fp32 out), weight slab 3
    dim3 o_grid(GN / 128, ROWS / 128);         // (8, 32)
    gemm_bf<<<o_grid, 256, GEMM_SMEM>>>(Chp, Clp,
                                        wh + 3 * (size_t)N2W, wl + 3 * (size_t)N2W,
                                        out, nullptr, nullptr);
}